// round 4
// baseline (speedup 1.0000x reference)
#include <cuda_runtime.h>
#include <cstdint>
#include <math_constants.h>

// Problem constants
#define DMODEL 512
#define NHEAD  8
#define DHEAD  64
#define LSEQ   1024
#define NB     8
#define MROWS  (LSEQ * NB)   // 8192

// Scratch (device globals; no allocations allowed)
__device__ float g_q[64 * 1024 * 64];    // [(b*8+h)][l][d]
__device__ float g_k[64 * 1024 * 64];
__device__ float g_v[64 * 1024 * 64];
__device__ float g_ctx[MROWS * DMODEL];  // [(l*8+b)][h*64+d]

// ---------------------------------------------------------------------------
// helpers
// ---------------------------------------------------------------------------
__device__ __forceinline__ uint32_t f2tf(float x) {
    uint32_t r;
    asm("cvt.rna.tf32.f32 %0, %1;" : "=r"(r) : "f"(x));
    return r;
}

// D (=C) += A * B, m16n8k8 tf32
__device__ __forceinline__ void mma8(float* c, const uint32_t* a, const uint32_t* b) {
    asm volatile(
        "mma.sync.aligned.m16n8k8.row.col.f32.tf32.tf32.f32 "
        "{%0,%1,%2,%3}, {%4,%5,%6,%7}, {%8,%9}, {%0,%1,%2,%3};\n"
        : "+f"(c[0]), "+f"(c[1]), "+f"(c[2]), "+f"(c[3])
        : "r"(a[0]), "r"(a[1]), "r"(a[2]), "r"(a[3]),
          "r"(b[0]), "r"(b[1]));
}

__device__ __forceinline__ uint32_t fbits(float x) { return __float_as_uint(x); }

// ---------------------------------------------------------------------------
// Kernel 1: QKV projections.  X[8192,512] @ W[512,512] + bias,
// scattered to g_q/g_k/g_v in [(b*8+h)][l][d] layout.
// blockIdx.z selects which projection. BM=BN=64, BK=16, 128 threads.
// ---------------------------------------------------------------------------
__global__ __launch_bounds__(128) void proj_kernel(
    const float* __restrict__ Xq, const float* __restrict__ Xk, const float* __restrict__ Xv,
    const float* __restrict__ Wq, const float* __restrict__ bq,
    const float* __restrict__ Wk, const float* __restrict__ bk,
    const float* __restrict__ Wv, const float* __restrict__ bv)
{
    const int z = blockIdx.z;
    const float* X    = (z == 0) ? Xq : (z == 1) ? Xk : Xv;
    const float* W    = (z == 0) ? Wq : (z == 1) ? Wk : Wv;
    const float* bias = (z == 0) ? bq : (z == 1) ? bk : bv;
    float* dst        = (z == 0) ? g_q : (z == 1) ? g_k : g_v;

    __shared__ float As[64][20];  // stride 20: conflict-free A-fragment reads
    __shared__ float Bs[16][72];  // stride 72: conflict-free B-fragment reads

    const int t = threadIdx.x;
    const int lane = t & 31, warp = t >> 5;
    const int g = lane >> 2, t4 = lane & 3;
    const int wm = warp >> 1, wn = warp & 1;

    const int rowBase = blockIdx.x * 64;
    const int colBase = blockIdx.y * 64;

    float acc[2][4][4];
#pragma unroll
    for (int mt = 0; mt < 2; mt++)
#pragma unroll
        for (int nt = 0; nt < 4; nt++)
#pragma unroll
            for (int i = 0; i < 4; i++) acc[mt][nt][i] = 0.f;

    for (int kt = 0; kt < DMODEL / 16; kt++) {
        // stage A tile (64x16) as tf32 bits
#pragma unroll
        for (int i = 0; i < 2; i++) {
            int idx = t + i * 128;          // 256 float4s
            int r = idx >> 2, c4 = idx & 3;
            float4 v = *(const float4*)(X + (size_t)(rowBase + r) * DMODEL + kt * 16 + c4 * 4);
            As[r][c4 * 4 + 0] = __uint_as_float(f2tf(v.x));
            As[r][c4 * 4 + 1] = __uint_as_float(f2tf(v.y));
            As[r][c4 * 4 + 2] = __uint_as_float(f2tf(v.z));
            As[r][c4 * 4 + 3] = __uint_as_float(f2tf(v.w));
        }
        // stage B tile (16x64)
#pragma unroll
        for (int i = 0; i < 2; i++) {
            int idx = t + i * 128;
            int r = idx >> 4, c4 = idx & 15;
            float4 v = *(const float4*)(W + (size_t)(kt * 16 + r) * DMODEL + colBase + c4 * 4);
            Bs[r][c4 * 4 + 0] = __uint_as_float(f2tf(v.x));
            Bs[r][c4 * 4 + 1] = __uint_as_float(f2tf(v.y));
            Bs[r][c4 * 4 + 2] = __uint_as_float(f2tf(v.z));
            Bs[r][c4 * 4 + 3] = __uint_as_float(f2tf(v.w));
        }
        __syncthreads();

#pragma unroll
        for (int kk = 0; kk < 16; kk += 8) {
            uint32_t a[2][4], b[4][2];
#pragma unroll
            for (int mt = 0; mt < 2; mt++) {
                int r0 = wm * 32 + mt * 16 + g;
                a[mt][0] = fbits(As[r0][kk + t4]);
                a[mt][1] = fbits(As[r0 + 8][kk + t4]);
                a[mt][2] = fbits(As[r0][kk + t4 + 4]);
                a[mt][3] = fbits(As[r0 + 8][kk + t4 + 4]);
            }
#pragma unroll
            for (int nt = 0; nt < 4; nt++) {
                int c = wn * 32 + nt * 8 + g;
                b[nt][0] = fbits(Bs[kk + t4][c]);
                b[nt][1] = fbits(Bs[kk + t4 + 4][c]);
            }
#pragma unroll
            for (int mt = 0; mt < 2; mt++)
#pragma unroll
                for (int nt = 0; nt < 4; nt++) mma8(acc[mt][nt], a[mt], b[nt]);
        }
        __syncthreads();
    }

    // epilogue: bias + scatter to [(b*8+h)][l][d]
#pragma unroll
    for (int mt = 0; mt < 2; mt++) {
#pragma unroll
        for (int nt = 0; nt < 4; nt++) {
#pragma unroll
            for (int i = 0; i < 4; i++) {
                int R = rowBase + wm * 32 + mt * 16 + g + ((i >= 2) ? 8 : 0);
                int C = colBase + wn * 32 + nt * 8 + 2 * t4 + (i & 1);
                float v = acc[mt][nt][i] + bias[C];
                int l = R >> 3, bb = R & 7;
                int h = C >> 6, d = C & 63;
                dst[(size_t)(((bb << 3) | h) * 1024 + l) * 64 + d] = v;
            }
        }
    }
}

// ---------------------------------------------------------------------------
// Kernel 2: fused flash attention per (b,h), 64-row q tiles, 64-key k tiles.
// 128 threads = 4 warps, each warp owns 16 q rows.
// ---------------------------------------------------------------------------
#define QS_STRIDE 68
#define KS_STRIDE 68
#define VS_STRIDE 72
#define PS_STRIDE 68
#define SMEM_FLOATS (64 * QS_STRIDE + 64 * KS_STRIDE + 64 * VS_STRIDE + 64 * PS_STRIDE)

__global__ __launch_bounds__(128) void attn_kernel(const float* __restrict__ mask)
{
    extern __shared__ float sm[];
    float* Qs = sm;                       // [64][68]
    float* Ks = Qs + 64 * QS_STRIDE;      // [64][68]
    float* Vs = Ks + 64 * KS_STRIDE;      // [64][72]
    float* Ps = Vs + 64 * VS_STRIDE;      // [64][68] (mask tile, then P tile)

    const int t = threadIdx.x;
    const int lane = t & 31, warp = t >> 5;
    const int g = lane >> 2, t4 = lane & 3;
    const int qt = blockIdx.x;   // 0..15
    const int bh = blockIdx.y;   // 0..63
    const int b = bh >> 3, h = bh & 7;

    const float* Qp = g_q + (size_t)(bh * 1024 + qt * 64) * 64;
    const float* Kp = g_k + (size_t)bh * 1024 * 64;
    const float* Vp = g_v + (size_t)bh * 1024 * 64;

    // load Q tile once (64x64), tf32
#pragma unroll
    for (int i = 0; i < 8; i++) {
        int idx = t + i * 128;            // 1024 float4s
        int r = idx >> 4, c4 = idx & 15;
        float4 v = *(const float4*)(Qp + r * 64 + c4 * 4);
        Qs[r * QS_STRIDE + c4 * 4 + 0] = __uint_as_float(f2tf(v.x));
        Qs[r * QS_STRIDE + c4 * 4 + 1] = __uint_as_float(f2tf(v.y));
        Qs[r * QS_STRIDE + c4 * 4 + 2] = __uint_as_float(f2tf(v.z));
        Qs[r * QS_STRIDE + c4 * 4 + 3] = __uint_as_float(f2tf(v.w));
    }

    float O[8][4];
#pragma unroll
    for (int nt = 0; nt < 8; nt++)
#pragma unroll
        for (int i = 0; i < 4; i++) O[nt][i] = 0.f;
    float m0 = -CUDART_INF_F, m1 = -CUDART_INF_F;
    float l0 = 0.f, l1 = 0.f;
    const int r0 = warp * 16 + g;

    for (int kt = 0; kt < 16; kt++) {
        __syncthreads();  // previous iteration's reads done (also covers Qs staging)
        // stage K, V (tf32) and mask tile (fp32, into Ps)
#pragma unroll
        for (int i = 0; i < 8; i++) {
            int idx = t + i * 128;
            int r = idx >> 4, c4 = idx & 15;
            float4 kv = *(const float4*)(Kp + (size_t)(kt * 64 + r) * 64 + c4 * 4);
            Ks[r * KS_STRIDE + c4 * 4 + 0] = __uint_as_float(f2tf(kv.x));
            Ks[r * KS_STRIDE + c4 * 4 + 1] = __uint_as_float(f2tf(kv.y));
            Ks[r * KS_STRIDE + c4 * 4 + 2] = __uint_as_float(f2tf(kv.z));
            Ks[r * KS_STRIDE + c4 * 4 + 3] = __uint_as_float(f2tf(kv.w));
            float4 vv = *(const float4*)(Vp + (size_t)(kt * 64 + r) * 64 + c4 * 4);
            Vs[r * VS_STRIDE + c4 * 4 + 0] = __uint_as_float(f2tf(vv.x));
            Vs[r * VS_STRIDE + c4 * 4 + 1] = __uint_as_float(f2tf(vv.y));
            Vs[r * VS_STRIDE + c4 * 4 + 2] = __uint_as_float(f2tf(vv.z));
            Vs[r * VS_STRIDE + c4 * 4 + 3] = __uint_as_float(f2tf(vv.w));
            float4 mv = *(const float4*)(mask + (size_t)(qt * 64 + r) * LSEQ + kt * 64 + c4 * 4);
            Ps[r * PS_STRIDE + c4 * 4 + 0] = mv.x;
            Ps[r * PS_STRIDE + c4 * 4 + 1] = mv.y;
            Ps[r * PS_STRIDE + c4 * 4 + 2] = mv.z;
            Ps[r * PS_STRIDE + c4 * 4 + 3] = mv.w;
        }
        __syncthreads();

        // S = Q K^T for this tile
        float S[8][4];
#pragma unroll
        for (int nt = 0; nt < 8; nt++)
#pragma unroll
            for (int i = 0; i < 4; i++) S[nt][i] = 0.f;

#pragma unroll
        for (int kk = 0; kk < 64; kk += 8) {
            uint32_t a[4];
            a[0] = fbits(Qs[r0 * QS_STRIDE + kk + t4]);
            a[1] = fbits(Qs[(r0 + 8) * QS_STRIDE + kk + t4]);
            a[2] = fbits(Qs[r0 * QS_STRIDE + kk + t4 + 4]);
            a[3] = fbits(Qs[(r0 + 8) * QS_STRIDE + kk + t4 + 4]);
#pragma unroll
            for (int nt = 0; nt < 8; nt++) {
                uint32_t bb[2];
                int key = nt * 8 + g;
                bb[0] = fbits(Ks[key * KS_STRIDE + kk + t4]);
                bb[1] = fbits(Ks[key * KS_STRIDE + kk + t4 + 4]);
                mma8(S[nt], a, bb);
            }
        }

        // scale + mask, online softmax
        const float scale = 0.125f;  // 1/sqrt(64)
        float mx0 = -CUDART_INF_F, mx1 = -CUDART_INF_F;
#pragma unroll
        for (int nt = 0; nt < 8; nt++) {
#pragma unroll
            for (int i = 0; i < 4; i++) {
                int rowLoc = r0 + ((i >= 2) ? 8 : 0);
                int col = nt * 8 + 2 * t4 + (i & 1);
                float s = S[nt][i] * scale + Ps[rowLoc * PS_STRIDE + col];
                S[nt][i] = s;
                if (i < 2) mx0 = fmaxf(mx0, s); else mx1 = fmaxf(mx1, s);
            }
        }
        mx0 = fmaxf(mx0, __shfl_xor_sync(0xffffffffu, mx0, 1));
        mx0 = fmaxf(mx0, __shfl_xor_sync(0xffffffffu, mx0, 2));
        mx1 = fmaxf(mx1, __shfl_xor_sync(0xffffffffu, mx1, 1));
        mx1 = fmaxf(mx1, __shfl_xor_sync(0xffffffffu, mx1, 2));

        float mn0 = fmaxf(m0, mx0), mn1 = fmaxf(m1, mx1);
        float al0 = __expf(m0 - mn0), al1 = __expf(m1 - mn1);
        m0 = mn0; m1 = mn1;

        float rs0 = 0.f, rs1 = 0.f;
#pragma unroll
        for (int nt = 0; nt < 8; nt++) {
#pragma unroll
            for (int i = 0; i < 4; i++) {
                float p = __expf(S[nt][i] - ((i < 2) ? mn0 : mn1));
                S[nt][i] = p;
                if (i < 2) rs0 += p; else rs1 += p;
            }
        }
        rs0 += __shfl_xor_sync(0xffffffffu, rs0, 1);
        rs0 += __shfl_xor_sync(0xffffffffu, rs0, 2);
        rs1 += __shfl_xor_sync(0xffffffffu, rs1, 1);
        rs1 += __shfl_xor_sync(0xffffffffu, rs1, 2);
        l0 = l0 * al0 + rs0;
        l1 = l1 * al1 + rs1;
#pragma unroll
        for (int nt = 0; nt < 8; nt++) {
            O[nt][0] *= al0; O[nt][1] *= al0;
            O[nt][2] *= al1; O[nt][3] *= al1;
        }

        // stage P (tf32) into Ps — warp-local rows only
#pragma unroll
        for (int nt = 0; nt < 8; nt++) {
#pragma unroll
            for (int i = 0; i < 4; i++) {
                int rowLoc = r0 + ((i >= 2) ? 8 : 0);
                int col = nt * 8 + 2 * t4 + (i & 1);
                Ps[rowLoc * PS_STRIDE + col] = __uint_as_float(f2tf(S[nt][i]));
            }
        }
        __syncwarp();

        // O += P V
#pragma unroll
        for (int kk = 0; kk < 64; kk += 8) {
            uint32_t a[4];
            a[0] = fbits(Ps[r0 * PS_STRIDE + kk + t4]);
            a[1] = fbits(Ps[(r0 + 8) * PS_STRIDE + kk + t4]);
            a[2] = fbits(Ps[r0 * PS_STRIDE + kk + t4 + 4]);
            a[3] = fbits(Ps[(r0 + 8) * PS_STRIDE + kk + t4 + 4]);
#pragma unroll
            for (int nt = 0; nt < 8; nt++) {
                uint32_t bb[2];
                bb[0] = fbits(Vs[(kk + t4) * VS_STRIDE + nt * 8 + g]);
                bb[1] = fbits(Vs[(kk + t4 + 4) * VS_STRIDE + nt * 8 + g]);
                mma8(O[nt], a, bb);
            }
        }
    }

    // normalize + write ctx as [(l*8+b)][h*64+d]
    float inv0 = 1.f / l0, inv1 = 1.f / l1;
#pragma unroll
    for (int nt = 0; nt < 8; nt++) {
#pragma unroll
        for (int i = 0; i < 4; i++) {
            int rowLoc = r0 + ((i >= 2) ? 8 : 0);
            int qg = qt * 64 + rowLoc;
            int d = nt * 8 + 2 * t4 + (i & 1);
            g_ctx[(size_t)(qg * 8 + b) * DMODEL + h * 64 + d] =
                O[nt][i] * ((i < 2) ? inv0 : inv1);
        }
    }
}

// ---------------------------------------------------------------------------
// Kernel 3: out = ctx @ Wo + bo  (plain row-major output)
// ---------------------------------------------------------------------------
__global__ __launch_bounds__(128) void outproj_kernel(
    const float* __restrict__ Wo, const float* __restrict__ bo,
    float* __restrict__ out)
{
    __shared__ float As[64][20];
    __shared__ float Bs[16][72];

    const int t = threadIdx.x;
    const int lane = t & 31, warp = t >> 5;
    const int g = lane >> 2, t4 = lane & 3;
    const int wm = warp >> 1, wn = warp & 1;

    const int rowBase = blockIdx.x * 64;
    const int colBase = blockIdx.y * 64;

    float acc[2][4][4];
#pragma unroll
    for (int mt = 0; mt < 2; mt++)
#pragma unroll
        for (int nt = 0; nt < 4; nt++)
#pragma unroll
            for (int i = 0; i < 4; i++) acc[mt][nt][i] = 0.f;

    for (int kt = 0; kt < DMODEL / 16; kt++) {
#pragma unroll
        for (int i = 0; i < 2; i++) {
            int idx = t + i * 128;
            int r = idx >> 2, c4 = idx & 3;
            float4 v = *(const float4*)(g_ctx + (size_t)(rowBase + r) * DMODEL + kt * 16 + c4 * 4);
            As[r][c4 * 4 + 0] = __uint_as_float(f2tf(v.x));
            As[r][c4 * 4 + 1] = __uint_as_float(f2tf(v.y));
            As[r][c4 * 4 + 2] = __uint_as_float(f2tf(v.z));
            As[r][c4 * 4 + 3] = __uint_as_float(f2tf(v.w));
        }
#pragma unroll
        for (int i = 0; i < 2; i++) {
            int idx = t + i * 128;
            int r = idx >> 4, c4 = idx & 15;
            float4 v = *(const float4*)(Wo + (size_t)(kt * 16 + r) * DMODEL + colBase + c4 * 4);
            Bs[r][c4 * 4 + 0] = __uint_as_float(f2tf(v.x));
            Bs[r][c4 * 4 + 1] = __uint_as_float(f2tf(v.y));
            Bs[r][c4 * 4 + 2] = __uint_as_float(f2tf(v.z));
            Bs[r][c4 * 4 + 3] = __uint_as_float(f2tf(v.w));
        }
        __syncthreads();

#pragma unroll
        for (int kk = 0; kk < 16; kk += 8) {
            uint32_t a[2][4], b[4][2];
#pragma unroll
            for (int mt = 0; mt < 2; mt++) {
                int r0 = wm * 32 + mt * 16 + g;
                a[mt][0] = fbits(As[r0][kk + t4]);
                a[mt][1] = fbits(As[r0 + 8][kk + t4]);
                a[mt][2] = fbits(As[r0][kk + t4 + 4]);
                a[mt][3] = fbits(As[r0 + 8][kk + t4 + 4]);
            }
#pragma unroll
            for (int nt = 0; nt < 4; nt++) {
                int c = wn * 32 + nt * 8 + g;
                b[nt][0] = fbits(Bs[kk + t4][c]);
                b[nt][1] = fbits(Bs[kk + t4 + 4][c]);
            }
#pragma unroll
            for (int mt = 0; mt < 2; mt++)
#pragma unroll
                for (int nt = 0; nt < 4; nt++) mma8(acc[mt][nt], a[mt], b[nt]);
        }
        __syncthreads();
    }

#pragma unroll
    for (int mt = 0; mt < 2; mt++) {
#pragma unroll
        for (int nt = 0; nt < 4; nt++) {
#pragma unroll
            for (int i = 0; i < 4; i++) {
                int R = rowBase + wm * 32 + mt * 16 + g + ((i >= 2) ? 8 : 0);
                int C = colBase + wn * 32 + nt * 8 + 2 * t4 + (i & 1);
                out[(size_t)R * DMODEL + C] = acc[mt][nt][i] + bo[C];
            }
        }
    }
}

// ---------------------------------------------------------------------------
// launch
// ---------------------------------------------------------------------------
extern "C" void kernel_launch(void* const* d_in, const int* in_sizes, int n_in,
                              void* d_out, int out_size)
{
    const float* Q    = (const float*)d_in[0];
    const float* K    = (const float*)d_in[1];
    const float* V    = (const float*)d_in[2];
    const float* mask = (const float*)d_in[3];
    const float* Wq   = (const float*)d_in[4];
    const float* bq   = (const float*)d_in[5];
    const float* Wk   = (const float*)d_in[6];
    const float* bk   = (const float*)d_in[7];
    const float* Wv   = (const float*)d_in[8];
    const float* bv   = (const float*)d_in[9];
    const float* Wo   = (const float*)d_in[10];
    const float* bo   = (const float*)d_in[11];
    float* out = (float*)d_out;

    const int smem_bytes = SMEM_FLOATS * (int)sizeof(float);  // 70656
    cudaFuncSetAttribute(attn_kernel, cudaFuncAttributeMaxDynamicSharedMemorySize, smem_bytes);

    proj_kernel<<<dim3(MROWS / 64, DMODEL / 64, 3), 128>>>(Q, K, V, Wq, bq, Wk, bk, Wv, bv);
    attn_kernel<<<dim3(LSEQ / 64, NB * NHEAD), 128, smem_bytes>>>(mask);
    outproj_kernel<<<dim3(MROWS / 64, DMODEL / 64), 128>>>(Wo, bo, out);
}

// round 8
// speedup vs baseline: 1.1153x; 1.1153x over previous
#include <cuda_runtime.h>
#include <cstdint>
#include <math_constants.h>

// Problem constants
#define DMODEL 512
#define NHEAD  8
#define DHEAD  64
#define LSEQ   1024
#define NB     8
#define MROWS  (LSEQ * NB)   // 8192

// Scratch (device globals; no allocations allowed)
__device__ float g_q[64 * 1024 * 64];    // [(b*8+h)][l][d]
__device__ float g_k[64 * 1024 * 64];
__device__ float g_v[64 * 1024 * 64];
__device__ float g_ctx[MROWS * DMODEL];  // [(l*8+b)][h*64+d]

// ---------------------------------------------------------------------------
// helpers
// ---------------------------------------------------------------------------
__device__ __forceinline__ uint32_t f2tf(float x) {
    uint32_t r;
    asm("cvt.rna.tf32.f32 %0, %1;" : "=r"(r) : "f"(x));
    return r;
}

// D (=C) += A * B, m16n8k8 tf32
__device__ __forceinline__ void mma8(float* c, const uint32_t* a, const uint32_t* b) {
    asm volatile(
        "mma.sync.aligned.m16n8k8.row.col.f32.tf32.tf32.f32 "
        "{%0,%1,%2,%3}, {%4,%5,%6,%7}, {%8,%9}, {%0,%1,%2,%3};\n"
        : "+f"(c[0]), "+f"(c[1]), "+f"(c[2]), "+f"(c[3])
        : "r"(a[0]), "r"(a[1]), "r"(a[2]), "r"(a[3]),
          "r"(b[0]), "r"(b[1]));
}

__device__ __forceinline__ uint32_t fbits(float x) { return __float_as_uint(x); }

__device__ __forceinline__ void cp16(void* dst_smem, const void* src) {
    uint32_t d = (uint32_t)__cvta_generic_to_shared(dst_smem);
    asm volatile("cp.async.ca.shared.global [%0], [%1], 16;\n" :: "r"(d), "l"(src));
}
__device__ __forceinline__ void cp_commit() {
    asm volatile("cp.async.commit_group;\n");
}
template <int N>
__device__ __forceinline__ void cp_wait() {
    asm volatile("cp.async.wait_group %0;\n" :: "n"(N));
}

// ---------------------------------------------------------------------------
// GEMM tile geometry (proj + outproj): BM=128, BN=64, BK=32, 256 threads
// ---------------------------------------------------------------------------
#define AS_STRIDE 36
#define BS_STRIDE 68
#define AS_STAGE  (128 * AS_STRIDE)
#define BS_STAGE  (32 * BS_STRIDE)
#define GEMM_SMEM_FLOATS (2 * AS_STAGE + 2 * BS_STAGE)
#define GEMM_SMEM_BYTES  (GEMM_SMEM_FLOATS * 4)

// stage A[128x32] + B[32x64] (raw fp32) for k-tile kt into buffer s
__device__ __forceinline__ void gemm_stage(
    float* As, float* Bs, int s,
    const float* __restrict__ X, const float* __restrict__ W,
    int rowBase, int colBase, int kt, int t)
{
    const int k0 = kt * 32;
    float* Ad = As + s * AS_STAGE;
    float* Bd = Bs + s * BS_STAGE;
#pragma unroll
    for (int i = 0; i < 4; i++) {           // 1024 float4s of A
        int idx = t + i * 256;
        int r = idx >> 3, c4 = idx & 7;
        cp16(Ad + r * AS_STRIDE + c4 * 4,
             X + (size_t)(rowBase + r) * DMODEL + k0 + c4 * 4);
    }
#pragma unroll
    for (int i = 0; i < 2; i++) {           // 512 float4s of B
        int idx = t + i * 256;
        int r = idx >> 4, c4 = idx & 15;
        cp16(Bd + r * BS_STRIDE + c4 * 4,
             W + (size_t)(k0 + r) * DMODEL + colBase + c4 * 4);
    }
    cp_commit();
}

// ---------------------------------------------------------------------------
// Kernel 1: QKV projections.  X[8192,512] @ W[512,512] + bias,
// scattered to g_q/g_k/g_v in [(b*8+h)][l][d] layout.
// blockIdx.z selects projection; blockIdx.y selects head (BN=64).
// ---------------------------------------------------------------------------
__global__ __launch_bounds__(256) void proj_kernel(
    const float* __restrict__ Xq, const float* __restrict__ Xk, const float* __restrict__ Xv,
    const float* __restrict__ Wq, const float* __restrict__ bq,
    const float* __restrict__ Wk, const float* __restrict__ bk,
    const float* __restrict__ Wv, const float* __restrict__ bv)
{
    const int z = blockIdx.z;
    const float* X    = (z == 0) ? Xq : (z == 1) ? Xk : Xv;
    const float* W    = (z == 0) ? Wq : (z == 1) ? Wk : Wv;
    const float* bias = (z == 0) ? bq : (z == 1) ? bk : bv;
    float* dst        = (z == 0) ? g_q : (z == 1) ? g_k : g_v;

    extern __shared__ float sm[];
    float* As = sm;
    float* Bs = sm + 2 * AS_STAGE;

    const int t = threadIdx.x;
    const int lane = t & 31, warp = t >> 5;
    const int g = lane >> 2, t4 = lane & 3;
    const int wm = warp >> 1, wn = warp & 1;

    const int rowBase = blockIdx.x * 128;
    const int colBase = blockIdx.y * 64;

    float acc[2][4][4];
#pragma unroll
    for (int mt = 0; mt < 2; mt++)
#pragma unroll
        for (int nt = 0; nt < 4; nt++)
#pragma unroll
            for (int i = 0; i < 4; i++) acc[mt][nt][i] = 0.f;

    gemm_stage(As, Bs, 0, X, W, rowBase, colBase, 0, t);

    for (int kt = 0; kt < DMODEL / 32; kt++) {
        const int cur = kt & 1;
        if (kt + 1 < DMODEL / 32) {
            gemm_stage(As, Bs, 1 - cur, X, W, rowBase, colBase, kt + 1, t);
            cp_wait<1>();
        } else {
            cp_wait<0>();
        }
        __syncthreads();

#pragma unroll
        for (int k8 = 0; k8 < 4; k8++) {
            const float* Ad = As + cur * AS_STAGE;
            const float* Bd = Bs + cur * BS_STAGE;
            uint32_t a[2][4];
#pragma unroll
            for (int mt = 0; mt < 2; mt++) {
                int r0 = wm * 32 + mt * 16 + g;
                const float* Ar0 = Ad + r0 * AS_STRIDE + k8 * 8;
                const float* Ar8 = Ar0 + 8 * AS_STRIDE;
                a[mt][0] = f2tf(Ar0[t4]);
                a[mt][1] = f2tf(Ar8[t4]);
                a[mt][2] = f2tf(Ar0[t4 + 4]);
                a[mt][3] = f2tf(Ar8[t4 + 4]);
            }
#pragma unroll
            for (int nt = 0; nt < 4; nt++) {
                int c = wn * 32 + nt * 8 + g;
                uint32_t b[2];
                b[0] = f2tf(Bd[(k8 * 8 + t4) * BS_STRIDE + c]);
                b[1] = f2tf(Bd[(k8 * 8 + t4 + 4) * BS_STRIDE + c]);
#pragma unroll
                for (int mt = 0; mt < 2; mt++) mma8(acc[mt][nt], a[mt], b);
            }
        }
        __syncthreads();
    }

    // epilogue: bias + scatter to [(b*8+h)][l][d]; h = blockIdx.y fixed
    const int h = blockIdx.y;
#pragma unroll
    for (int mt = 0; mt < 2; mt++) {
#pragma unroll
        for (int nt = 0; nt < 4; nt++) {
#pragma unroll
            for (int i = 0; i < 4; i++) {
                int R = rowBase + wm * 32 + mt * 16 + g + ((i >= 2) ? 8 : 0);
                int C = colBase + wn * 32 + nt * 8 + 2 * t4 + (i & 1);
                float v = acc[mt][nt][i] + bias[C];
                int l = R >> 3, bb = R & 7;
                int d = C & 63;
                dst[(size_t)(((bb << 3) | h) * 1024 + l) * 64 + d] = v;
            }
        }
    }
}

// ---------------------------------------------------------------------------
// Kernel 2: fused flash attention per (b,h), 64-row q tiles, 64-key k tiles.
// 128 threads = 4 warps, each warp owns 16 q rows.  (unchanged — control)
// ---------------------------------------------------------------------------
#define QS_STRIDE 68
#define KS_STRIDE 68
#define VS_STRIDE 72
#define PS_STRIDE 68
#define SMEM_FLOATS (64 * QS_STRIDE + 64 * KS_STRIDE + 64 * VS_STRIDE + 64 * PS_STRIDE)

__global__ __launch_bounds__(128) void attn_kernel(const float* __restrict__ mask)
{
    extern __shared__ float sm[];
    float* Qs = sm;                       // [64][68]
    float* Ks = Qs + 64 * QS_STRIDE;      // [64][68]
    float* Vs = Ks + 64 * KS_STRIDE;      // [64][72]
    float* Ps = Vs + 64 * VS_STRIDE;      // [64][68] (mask tile, then P tile)

    const int t = threadIdx.x;
    const int lane = t & 31, warp = t >> 5;
    const int g = lane >> 2, t4 = lane & 3;
    const int qt = blockIdx.x;   // 0..15
    const int bh = blockIdx.y;   // 0..63
    const int b = bh >> 3, h = bh & 7;

    const float* Qp = g_q + (size_t)(bh * 1024 + qt * 64) * 64;
    const float* Kp = g_k + (size_t)bh * 1024 * 64;
    const float* Vp = g_v + (size_t)bh * 1024 * 64;

    // load Q tile once (64x64), tf32
#pragma unroll
    for (int i = 0; i < 8; i++) {
        int idx = t + i * 128;            // 1024 float4s
        int r = idx >> 4, c4 = idx & 15;
        float4 v = *(const float4*)(Qp + r * 64 + c4 * 4);
        Qs[r * QS_STRIDE + c4 * 4 + 0] = __uint_as_float(f2tf(v.x));
        Qs[r * QS_STRIDE + c4 * 4 + 1] = __uint_as_float(f2tf(v.y));
        Qs[r * QS_STRIDE + c4 * 4 + 2] = __uint_as_float(f2tf(v.z));
        Qs[r * QS_STRIDE + c4 * 4 + 3] = __uint_as_float(f2tf(v.w));
    }

    float O[8][4];
#pragma unroll
    for (int nt = 0; nt < 8; nt++)
#pragma unroll
        for (int i = 0; i < 4; i++) O[nt][i] = 0.f;
    float m0 = -CUDART_INF_F, m1 = -CUDART_INF_F;
    float l0 = 0.f, l1 = 0.f;
    const int r0 = warp * 16 + g;

    for (int kt = 0; kt < 16; kt++) {
        __syncthreads();  // previous iteration's reads done (also covers Qs staging)
        // stage K, V (tf32) and mask tile (fp32, into Ps)
#pragma unroll
        for (int i = 0; i < 8; i++) {
            int idx = t + i * 128;
            int r = idx >> 4, c4 = idx & 15;
            float4 kv = *(const float4*)(Kp + (size_t)(kt * 64 + r) * 64 + c4 * 4);
            Ks[r * KS_STRIDE + c4 * 4 + 0] = __uint_as_float(f2tf(kv.x));
            Ks[r * KS_STRIDE + c4 * 4 + 1] = __uint_as_float(f2tf(kv.y));
            Ks[r * KS_STRIDE + c4 * 4 + 2] = __uint_as_float(f2tf(kv.z));
            Ks[r * KS_STRIDE + c4 * 4 + 3] = __uint_as_float(f2tf(kv.w));
            float4 vv = *(const float4*)(Vp + (size_t)(kt * 64 + r) * 64 + c4 * 4);
            Vs[r * VS_STRIDE + c4 * 4 + 0] = __uint_as_float(f2tf(vv.x));
            Vs[r * VS_STRIDE + c4 * 4 + 1] = __uint_as_float(f2tf(vv.y));
            Vs[r * VS_STRIDE + c4 * 4 + 2] = __uint_as_float(f2tf(vv.z));
            Vs[r * VS_STRIDE + c4 * 4 + 3] = __uint_as_float(f2tf(vv.w));
            float4 mv = *(const float4*)(mask + (size_t)(qt * 64 + r) * LSEQ + kt * 64 + c4 * 4);
            Ps[r * PS_STRIDE + c4 * 4 + 0] = mv.x;
            Ps[r * PS_STRIDE + c4 * 4 + 1] = mv.y;
            Ps[r * PS_STRIDE + c4 * 4 + 2] = mv.z;
            Ps[r * PS_STRIDE + c4 * 4 + 3] = mv.w;
        }
        __syncthreads();

        // S = Q K^T for this tile
        float S[8][4];
#pragma unroll
        for (int nt = 0; nt < 8; nt++)
#pragma unroll
            for (int i = 0; i < 4; i++) S[nt][i] = 0.f;

#pragma unroll
        for (int kk = 0; kk < 64; kk += 8) {
            uint32_t a[4];
            a[0] = fbits(Qs[r0 * QS_STRIDE + kk + t4]);
            a[1] = fbits(Qs[(r0 + 8) * QS_STRIDE + kk + t4]);
            a[2] = fbits(Qs[r0 * QS_STRIDE + kk + t4 + 4]);
            a[3] = fbits(Qs[(r0 + 8) * QS_STRIDE + kk + t4 + 4]);
#pragma unroll
            for (int nt = 0; nt < 8; nt++) {
                uint32_t bb[2];
                int key = nt * 8 + g;
                bb[0] = fbits(Ks[key * KS_STRIDE + kk + t4]);
                bb[1] = fbits(Ks[key * KS_STRIDE + kk + t4 + 4]);
                mma8(S[nt], a, bb);
            }
        }

        // scale + mask, online softmax
        const float scale = 0.125f;  // 1/sqrt(64)
        float mx0 = -CUDART_INF_F, mx1 = -CUDART_INF_F;
#pragma unroll
        for (int nt = 0; nt < 8; nt++) {
#pragma unroll
            for (int i = 0; i < 4; i++) {
                int rowLoc = r0 + ((i >= 2) ? 8 : 0);
                int col = nt * 8 + 2 * t4 + (i & 1);
                float s = S[nt][i] * scale + Ps[rowLoc * PS_STRIDE + col];
                S[nt][i] = s;
                if (i < 2) mx0 = fmaxf(mx0, s); else mx1 = fmaxf(mx1, s);
            }
        }
        mx0 = fmaxf(mx0, __shfl_xor_sync(0xffffffffu, mx0, 1));
        mx0 = fmaxf(mx0, __shfl_xor_sync(0xffffffffu, mx0, 2));
        mx1 = fmaxf(mx1, __shfl_xor_sync(0xffffffffu, mx1, 1));
        mx1 = fmaxf(mx1, __shfl_xor_sync(0xffffffffu, mx1, 2));

        float mn0 = fmaxf(m0, mx0), mn1 = fmaxf(m1, mx1);
        float al0 = __expf(m0 - mn0), al1 = __expf(m1 - mn1);
        m0 = mn0; m1 = mn1;

        float rs0 = 0.f, rs1 = 0.f;
#pragma unroll
        for (int nt = 0; nt < 8; nt++) {
#pragma unroll
            for (int i = 0; i < 4; i++) {
                float p = __expf(S[nt][i] - ((i < 2) ? mn0 : mn1));
                S[nt][i] = p;
                if (i < 2) rs0 += p; else rs1 += p;
            }
        }
        rs0 += __shfl_xor_sync(0xffffffffu, rs0, 1);
        rs0 += __shfl_xor_sync(0xffffffffu, rs0, 2);
        rs1 += __shfl_xor_sync(0xffffffffu, rs1, 1);
        rs1 += __shfl_xor_sync(0xffffffffu, rs1, 2);
        l0 = l0 * al0 + rs0;
        l1 = l1 * al1 + rs1;
#pragma unroll
        for (int nt = 0; nt < 8; nt++) {
            O[nt][0] *= al0; O[nt][1] *= al0;
            O[nt][2] *= al1; O[nt][3] *= al1;
        }

        // stage P (tf32) into Ps — warp-local rows only
#pragma unroll
        for (int nt = 0; nt < 8; nt++) {
#pragma unroll
            for (int i = 0; i < 4; i++) {
                int rowLoc = r0 + ((i >= 2) ? 8 : 0);
                int col = nt * 8 + 2 * t4 + (i & 1);
                Ps[rowLoc * PS_STRIDE + col] = __uint_as_float(f2tf(S[nt][i]));
            }
        }
        __syncwarp();

        // O += P V
#pragma unroll
        for (int kk = 0; kk < 64; kk += 8) {
            uint32_t a[4];
            a[0] = fbits(Ps[r0 * PS_STRIDE + kk + t4]);
            a[1] = fbits(Ps[(r0 + 8) * PS_STRIDE + kk + t4]);
            a[2] = fbits(Ps[r0 * PS_STRIDE + kk + t4 + 4]);
            a[3] = fbits(Ps[(r0 + 8) * PS_STRIDE + kk + t4 + 4]);
#pragma unroll
            for (int nt = 0; nt < 8; nt++) {
                uint32_t bb[2];
                bb[0] = fbits(Vs[(kk + t4) * VS_STRIDE + nt * 8 + g]);
                bb[1] = fbits(Vs[(kk + t4 + 4) * VS_STRIDE + nt * 8 + g]);
                mma8(O[nt], a, bb);
            }
        }
    }

    // normalize + write ctx as [(l*8+b)][h*64+d]
    float inv0 = 1.f / l0, inv1 = 1.f / l1;
#pragma unroll
    for (int nt = 0; nt < 8; nt++) {
#pragma unroll
        for (int i = 0; i < 4; i++) {
            int rowLoc = r0 + ((i >= 2) ? 8 : 0);
            int qg = qt * 64 + rowLoc;
            int d = nt * 8 + 2 * t4 + (i & 1);
            g_ctx[(size_t)(qg * 8 + b) * DMODEL + h * 64 + d] =
                O[nt][i] * ((i < 2) ? inv0 : inv1);
        }
    }
}

// ---------------------------------------------------------------------------
// Kernel 3: out = ctx @ Wo + bo  (row-major output), same GEMM design
// ---------------------------------------------------------------------------
__global__ __launch_bounds__(256) void outproj_kernel(
    const float* __restrict__ Wo, const float* __restrict__ bo,
    float* __restrict__ out)
{
    extern __shared__ float sm[];
    float* As = sm;
    float* Bs = sm + 2 * AS_STAGE;

    const int t = threadIdx.x;
    const int lane = t & 31, warp = t >> 5;
    const int g = lane >> 2, t4 = lane & 3;
    const int wm = warp >> 1, wn = warp & 1;

    const int rowBase = blockIdx.x * 128;
    const int colBase = blockIdx.y * 64;

    float acc[2][4][4];
#pragma unroll
    for (int mt = 0; mt < 2; mt++)
#pragma unroll
        for (int nt = 0; nt < 4; nt++)
#pragma unroll
            for (int i = 0; i < 4; i++) acc[mt][nt][i] = 0.f;

    gemm_stage(As, Bs, 0, g_ctx, Wo, rowBase, colBase, 0, t);

    for (int kt = 0; kt < DMODEL / 32; kt++) {
        const int cur = kt & 1;
        if (kt + 1 < DMODEL / 32) {
            gemm_stage(As, Bs, 1 - cur, g_ctx, Wo, rowBase, colBase, kt + 1, t);
            cp_wait<1>();
        } else {
            cp_wait<0>();
        }
        __syncthreads();

#pragma unroll
        for (int k8 = 0; k8 < 4; k8++) {
            const float* Ad = As + cur * AS_STAGE;
            const float* Bd = Bs + cur * BS_STAGE;
            uint32_t a[2][4];
#pragma unroll
            for (int mt = 0; mt < 2; mt++) {
                int r0 = wm * 32 + mt * 16 + g;
                const float* Ar0 = Ad + r0 * AS_STRIDE + k8 * 8;
                const float* Ar8 = Ar0 + 8 * AS_STRIDE;
                a[mt][0] = f2tf(Ar0[t4]);
                a[mt][1] = f2tf(Ar8[t4]);
                a[mt][2] = f2tf(Ar0[t4 + 4]);
                a[mt][3] = f2tf(Ar8[t4 + 4]);
            }
#pragma unroll
            for (int nt = 0; nt < 4; nt++) {
                int c = wn * 32 + nt * 8 + g;
                uint32_t b[2];
                b[0] = f2tf(Bd[(k8 * 8 + t4) * BS_STRIDE + c]);
                b[1] = f2tf(Bd[(k8 * 8 + t4 + 4) * BS_STRIDE + c]);
#pragma unroll
                for (int mt = 0; mt < 2; mt++) mma8(acc[mt][nt], a[mt], b);
            }
        }
        __syncthreads();
    }

#pragma unroll
    for (int mt = 0; mt < 2; mt++) {
#pragma unroll
        for (int nt = 0; nt < 4; nt++) {
#pragma unroll
            for (int i = 0; i < 4; i++) {
                int R = rowBase + wm * 32 + mt * 16 + g + ((i >= 2) ? 8 : 0);
                int C = colBase + wn * 32 + nt * 8 + 2 * t4 + (i & 1);
                out[(size_t)R * DMODEL + C] = acc[mt][nt][i] + bo[C];
            }
        }
    }
}

// ---------------------------------------------------------------------------
// launch
// ---------------------------------------------------------------------------
extern "C" void kernel_launch(void* const* d_in, const int* in_sizes, int n_in,
                              void* d_out, int out_size)
{
    const float* Q    = (const float*)d_in[0];
    const float* K    = (const float*)d_in[1];
    const float* V    = (const float*)d_in[2];
    const float* mask = (const float*)d_in[3];
    const float* Wq   = (const float*)d_in[4];
    const float* bq   = (const float*)d_in[5];
    const float* Wk   = (const float*)d_in[6];
    const float* bk   = (const float*)d_in[7];
    const float* Wv   = (const float*)d_in[8];
    const float* bv   = (const float*)d_in[9];
    const float* Wo   = (const float*)d_in[10];
    const float* bo   = (const float*)d_in[11];
    float* out = (float*)d_out;

    const int attn_smem = SMEM_FLOATS * (int)sizeof(float);   // 70656
    cudaFuncSetAttribute(attn_kernel, cudaFuncAttributeMaxDynamicSharedMemorySize, attn_smem);
    cudaFuncSetAttribute(proj_kernel, cudaFuncAttributeMaxDynamicSharedMemorySize, GEMM_SMEM_BYTES);
    cudaFuncSetAttribute(outproj_kernel, cudaFuncAttributeMaxDynamicSharedMemorySize, GEMM_SMEM_BYTES);

    proj_kernel<<<dim3(MROWS / 128, NHEAD, 3), 256, GEMM_SMEM_BYTES>>>(
        Q, K, V, Wq, bq, Wk, bk, Wv, bv);
    attn_kernel<<<dim3(LSEQ / 64, NB * NHEAD), 128, attn_smem>>>(mask);
    outproj_kernel<<<dim3(MROWS / 128, DMODEL / 64), 256, GEMM_SMEM_BYTES>>>(Wo, bo, out);
}